// round 4
// baseline (speedup 1.0000x reference)
#include <cuda_runtime.h>

// Problem constants (fixed by the reference).
#define Bn 4096
#define Tn 2048
#define Hn 64
#define G4 256   // 4*H gate rows

// Per-block partial loss sums (no alloc allowed -> device global scratch).
__device__ float g_partial[Bn];

// ---------- packed f32x2 helpers (FFMA2 path, sm_103a) ----------
__device__ __forceinline__ unsigned long long pack2(float x, float y) {
    unsigned long long r;
    asm("mov.b64 %0, {%1, %2};" : "=l"(r) : "f"(x), "f"(y));
    return r;
}
__device__ __forceinline__ void unpack2(unsigned long long v, float& x, float& y) {
    asm("mov.b64 {%0, %1}, %2;" : "=f"(x), "=f"(y) : "l"(v));
}
__device__ __forceinline__ void ffma2(unsigned long long& d,
                                      unsigned long long a,
                                      unsigned long long b) {
    // d = a * b + d  (two independent fp32 lanes per issue slot)
    asm("fma.rn.f32x2 %0, %1, %2, %0;" : "+l"(d) : "l"(a), "l"(b));
}

// ---------- activations ----------
__device__ __forceinline__ float sigm(float x) {
    // 1/(1+e^-x); __expf overflow to +inf gives 0 correctly via fast div.
    return __fdividef(1.0f, 1.0f + __expf(-x));
}
__device__ __forceinline__ float tanh_f(float x) {
    // tanh via e^{-2|x|}: never overflows; rel err ~1e-6.
    float a = fabsf(x);
    float e = __expf(-2.0f * a);
    float r = __fdividef(1.0f - e, 1.0f + e);
    return copysignf(r, x);
}

// ---------- padded copy: out[1 .. 1+B*T) = padded ----------
__global__ void copy_pad_kernel(const float4* __restrict__ src,
                                float* __restrict__ dst, int n4) {
    int i = blockIdx.x * blockDim.x + threadIdx.x;
    if (i < n4) {
        float4 v = src[i];
        int j = 4 * i;
        dst[j + 0] = v.x;
        dst[j + 1] = v.y;
        dst[j + 2] = v.z;
        dst[j + 3] = v.w;
    }
}

// ---------- main LSTM kernel: one CTA per batch element ----------
__global__ __launch_bounds__(256, 2)
void lstm_kernel(const float* __restrict__ padded,
                 const int*   __restrict__ seq_lengths,
                 const float* __restrict__ enc_Wih,
                 const float* __restrict__ enc_Whh,
                 const float* __restrict__ enc_b,
                 const float* __restrict__ enc_linW,
                 const float* __restrict__ enc_linb,
                 const float* __restrict__ dec_linW,
                 const float* __restrict__ dec_linb,
                 const float* __restrict__ dec_Wih,
                 const float* __restrict__ dec_Whh,
                 const float* __restrict__ dec_b,
                 const float* __restrict__ outW,
                 const float* __restrict__ outb,
                 float* __restrict__ out) {
    __shared__ float4 sh_h4[Hn / 4];   // hidden state, 16B-aligned for LDS.128
    __shared__ float  sh_g[G4];        // gate pre-activations
    __shared__ float  sh_hz[4];        // bottleneck (3 used)
    __shared__ float  xbuf[Tn];        // this sequence's inputs

    const int b    = blockIdx.x;
    const int t    = threadIdx.x;      // gate row owned by this thread
    const int lane = t & 31;

    float* sh_h = (float*)sh_h4;

    // Prefetch the input sequence into SMEM (also reused for the loss).
    const float* xin = padded + (size_t)b * Tn;
    for (int i = t; i < Tn; i += 256) xbuf[i] = xin[i];
    if (t < Hn) sh_h[t] = 0.0f;

    const int seqlen = seq_lengths[b];

    // Encoder weights -> registers (row t of Whh, packed as f32x2).
    unsigned long long w[32];
    {
        const float4* wp = (const float4*)(enc_Whh + t * Hn);
#pragma unroll
        for (int k = 0; k < 16; k++) {
            float4 v   = wp[k];
            w[2 * k]     = pack2(v.x, v.y);
            w[2 * k + 1] = pack2(v.z, v.w);
        }
    }
    float wih  = enc_Wih[t];
    float bias = enc_b[t];
    float c_reg = 0.0f;               // cell state lives in threads 0..63

    __syncthreads();

    // ---- encoder: state freezes at seqlen, so just stop there ----
    for (int s = 0; s < seqlen; s++) {
        float x = xbuf[s];
        const ulonglong2* hq = (const ulonglong2*)sh_h4;
        unsigned long long a0 = 0ull, a1 = 0ull;
#pragma unroll
        for (int k = 0; k < 16; k++) {
            ulonglong2 hv = hq[k];     // broadcast LDS.128
            ffma2(a0, w[2 * k],     hv.x);
            ffma2(a1, w[2 * k + 1], hv.y);
        }
        float p0, p1, p2, p3;
        unpack2(a0, p0, p1);
        unpack2(a1, p2, p3);
        sh_g[t] = (p0 + p1) + (p2 + p3) + __fmaf_rn(x, wih, bias);
        __syncthreads();
        if (t < Hn) {
            float gi = sh_g[t],           gf = sh_g[Hn + t];
            float gg = sh_g[2 * Hn + t],  go = sh_g[3 * Hn + t];
            c_reg   = sigm(gf) * c_reg + sigm(gi) * tanh_f(gg);
            sh_h[t] = sigm(go) * tanh_f(c_reg);
        }
        __syncthreads();
    }

    // ---- bottleneck: hz = sigmoid(h @ enc_linW.T + enc_linb) ----
    if (t < 3) {
        float s = enc_linb[t];
        const float* wl = enc_linW + t * Hn;
#pragma unroll 8
        for (int j = 0; j < Hn; j++) s = __fmaf_rn(wl[j], sh_h[j], s);
        float z = sigm(s);
        sh_hz[t] = z;
        out[1 + 2 * (size_t)Bn * Tn + (size_t)b * 3 + t] = z;
    }
    __syncthreads();

    // hd = hz @ dec_linW.T + dec_linb  (decoder initial hidden, NOT activated)
    if (t < Hn) {
        float hd = dec_linb[t]
                 + dec_linW[t * 3 + 0] * sh_hz[0]
                 + dec_linW[t * 3 + 1] * sh_hz[1]
                 + dec_linW[t * 3 + 2] * sh_hz[2];
        sh_h[t] = hd;                  // c_reg carries over from encoder
    }

    // Decoder weights -> registers.
    {
        const float4* wp = (const float4*)(dec_Whh + t * Hn);
#pragma unroll
        for (int k = 0; k < 16; k++) {
            float4 v   = wp[k];
            w[2 * k]     = pack2(v.x, v.y);
            w[2 * k + 1] = pack2(v.z, v.w);
        }
    }
    wih  = dec_Wih[t];
    bias = dec_b[t];
    float ow0 = outW[lane];            // y projection, per-lane
    float ow1 = outW[lane + 32];
    float ob  = outb[0];
    __syncthreads();

    // ---- decoder: full T steps, scalar feedback y -> x ----
    float  x    = 0.0f;
    float  lacc = 0.0f;
    float* out_y = out + 1 + (size_t)Bn * Tn + (size_t)b * Tn;

    for (int s = 0; s < Tn; s++) {
        const ulonglong2* hq = (const ulonglong2*)sh_h4;
        unsigned long long a0 = 0ull, a1 = 0ull;
#pragma unroll
        for (int k = 0; k < 16; k++) {
            ulonglong2 hv = hq[k];
            ffma2(a0, w[2 * k],     hv.x);
            ffma2(a1, w[2 * k + 1], hv.y);
        }
        float p0, p1, p2, p3;
        unpack2(a0, p0, p1);
        unpack2(a1, p2, p3);
        sh_g[t] = (p0 + p1) + (p2 + p3) + __fmaf_rn(x, wih, bias);
        __syncthreads();
        if (t < Hn) {
            float gi = sh_g[t],           gf = sh_g[Hn + t];
            float gg = sh_g[2 * Hn + t],  go = sh_g[3 * Hn + t];
            c_reg   = sigm(gf) * c_reg + sigm(gi) * tanh_f(gg);
            sh_h[t] = sigm(go) * tanh_f(c_reg);
        }
        __syncthreads();

        // y = h @ outW.T + outb — every warp computes it redundantly
        // (bitwise identical inputs -> identical y) so no third barrier.
        float p = sh_h[lane] * ow0 + sh_h[lane + 32] * ow1;
#pragma unroll
        for (int off = 16; off; off >>= 1)
            p += __shfl_xor_sync(0xffffffffu, p, off);
        float y = p + ob;

        if (t == 0) {
            out_y[s] = y;
            if (s < seqlen) {
                float d = xbuf[s] - y;
                lacc = __fmaf_rn(d, d, lacc);
            }
        }
        x = y;
    }

    if (t == 0) g_partial[b] = lacc;
}

// ---------- deterministic loss reduction ----------
__global__ void finalize_kernel(const int* __restrict__ seq_lengths,
                                float* __restrict__ out) {
    __shared__ double    ssum[256];
    __shared__ long long scnt[256];
    int tid = threadIdx.x;
    double    s = 0.0;
    long long c = 0;
    for (int i = tid; i < Bn; i += 256) {     // fixed order -> deterministic
        s += (double)g_partial[i];
        c += (long long)seq_lengths[i];
    }
    ssum[tid] = s;
    scnt[tid] = c;
    __syncthreads();
    for (int off = 128; off; off >>= 1) {     // fixed tree -> deterministic
        if (tid < off) {
            ssum[tid] += ssum[tid + off];
            scnt[tid] += scnt[tid + off];
        }
        __syncthreads();
    }
    if (tid == 0) out[0] = (float)(ssum[0] / (double)scnt[0]);
}

extern "C" void kernel_launch(void* const* d_in, const int* in_sizes, int n_in,
                              void* d_out, int out_size) {
    const float* padded   = (const float*)d_in[0];
    const int*   seql     = (const int*)  d_in[1];
    const float* enc_Wih  = (const float*)d_in[2];
    const float* enc_Whh  = (const float*)d_in[3];
    const float* enc_b    = (const float*)d_in[4];
    const float* enc_linW = (const float*)d_in[5];
    const float* enc_linb = (const float*)d_in[6];
    const float* dec_linW = (const float*)d_in[7];
    const float* dec_linb = (const float*)d_in[8];
    const float* dec_Wih  = (const float*)d_in[9];
    const float* dec_Whh  = (const float*)d_in[10];
    const float* dec_b    = (const float*)d_in[11];
    const float* outW     = (const float*)d_in[12];
    const float* outb     = (const float*)d_in[13];
    float* out = (float*)d_out;

    // out layout: [loss(1) | padded(B*T) | output(B*T) | hz(B*3)]
    const int n4 = (Bn * Tn) / 4;  // 2,097,152 float4s
    copy_pad_kernel<<<(n4 + 255) / 256, 256>>>((const float4*)padded, out + 1, n4);

    lstm_kernel<<<Bn, 256>>>(padded, seql,
                             enc_Wih, enc_Whh, enc_b,
                             enc_linW, enc_linb,
                             dec_linW, dec_linb,
                             dec_Wih, dec_Whh, dec_b,
                             outW, outb, out);

    finalize_kernel<<<1, 256>>>(seql, out);
}

// round 5
// speedup vs baseline: 1.2750x; 1.2750x over previous
#include <cuda_runtime.h>

// Problem constants (fixed by the reference).
#define Bn 4096
#define Tn 2048
#define Hn 64

// Per-block partial loss sums (no alloc allowed -> device global scratch).
__device__ float g_partial[Bn];

// ---------- packed f32x2 helpers (FFMA2 path, sm_103a) ----------
__device__ __forceinline__ unsigned long long pack2(float x, float y) {
    unsigned long long r;
    asm("mov.b64 %0, {%1, %2};" : "=l"(r) : "f"(x), "f"(y));
    return r;
}
__device__ __forceinline__ void unpack2(unsigned long long v, float& x, float& y) {
    asm("mov.b64 {%0, %1}, %2;" : "=f"(x), "=f"(y) : "l"(v));
}
__device__ __forceinline__ void ffma2(unsigned long long& d,
                                      unsigned long long a,
                                      unsigned long long b) {
    asm("fma.rn.f32x2 %0, %1, %2, %0;" : "+l"(d) : "l"(a), "l"(b));
}

// ---------- activations ----------
__device__ __forceinline__ float sigm(float x) {
    return __fdividef(1.0f, 1.0f + __expf(-x));
}
__device__ __forceinline__ float tanh_f(float x) {
    float a = fabsf(x);
    float e = __expf(-2.0f * a);
    float r = __fdividef(1.0f - e, 1.0f + e);
    return copysignf(r, x);
}

// ---------- padded copy: out[1 .. 1+B*T) = padded ----------
__global__ void copy_pad_kernel(const float4* __restrict__ src,
                                float* __restrict__ dst, int n4) {
    int i = blockIdx.x * blockDim.x + threadIdx.x;
    if (i < n4) {
        float4 v = src[i];
        int j = 4 * i;
        dst[j + 0] = v.x;
        dst[j + 1] = v.y;
        dst[j + 2] = v.z;
        dst[j + 3] = v.w;
    }
}

// ---------- main LSTM kernel: one CTA (128 threads) per batch element ----------
// Thread pair (2u, 2u+1) owns hidden unit u:
//   even thread: gate rows (u, 64+u)      = (i, f)
//   odd  thread: gate rows (128+u, 192+u) = (g, o)
// One barrier per step; h double-buffered (ping-pong).
__global__ __launch_bounds__(128, 3)
void lstm_kernel(const float* __restrict__ padded,
                 const int*   __restrict__ seq_lengths,
                 const float* __restrict__ enc_Wih,
                 const float* __restrict__ enc_Whh,
                 const float* __restrict__ enc_b,
                 const float* __restrict__ enc_linW,
                 const float* __restrict__ enc_linb,
                 const float* __restrict__ dec_linW,
                 const float* __restrict__ dec_linb,
                 const float* __restrict__ dec_Wih,
                 const float* __restrict__ dec_Whh,
                 const float* __restrict__ dec_b,
                 const float* __restrict__ outW,
                 const float* __restrict__ outb,
                 float* __restrict__ out) {
    __shared__ float4 hb4[2][Hn / 4];   // ping-pong hidden state
    __shared__ float4 sh_ow4[Hn / 4];   // outW staged for decoder fold
    __shared__ float  xbuf[Tn];         // input sequence
    __shared__ float  sh_s[4];          // bottleneck hz

    const int  b    = blockIdx.x;
    const int  t    = threadIdx.x;
    const int  u    = t >> 1;
    const bool even = !(t & 1);
    const int  lane = t & 31;

    float* hb0   = (float*)hb4[0];
    float* sh_ow = (float*)sh_ow4;

    const int rA = even ? u        : 128 + u;
    const int rB = even ? 64 + u   : 192 + u;

    // Prefetch input sequence + init state + stage outW.
    const float* xin = padded + (size_t)b * Tn;
    for (int i = t; i < Tn; i += 128) xbuf[i] = xin[i];
    if (t < Hn) { hb0[t] = 0.0f; sh_ow[t] = outW[t]; }

    const int seqlen = seq_lengths[b];

    // Encoder weights -> registers (2 rows x 64 = 64 f32x2 pairs).
    unsigned long long wA[32], wB[32];
    {
        const float4* pA = (const float4*)(enc_Whh + rA * Hn);
        const float4* pB = (const float4*)(enc_Whh + rB * Hn);
#pragma unroll
        for (int k = 0; k < 16; k++) {
            float4 a = pA[k];
            wA[2 * k]     = pack2(a.x, a.y);
            wA[2 * k + 1] = pack2(a.z, a.w);
            float4 c = pB[k];
            wB[2 * k]     = pack2(c.x, c.y);
            wB[2 * k + 1] = pack2(c.z, c.w);
        }
    }
    float wihA = enc_Wih[rA], wihB = enc_Wih[rB];
    float bsA  = enc_b[rA],   bsB  = enc_b[rB];
    float c_reg = 0.0f;                 // cell state (replicated in pair)

    __syncthreads();

    // ---- encoder: state freezes at seqlen -> stop there ----
    for (int s = 0; s < seqlen; s++) {
        const ulonglong2* hq = (const ulonglong2*)hb4[s & 1];
        float* wout = (float*)hb4[(s + 1) & 1];

        unsigned long long aA0 = 0ull, aA1 = 0ull, aB0 = 0ull, aB1 = 0ull;
#pragma unroll
        for (int k = 0; k < 16; k++) {
            ulonglong2 hv = hq[k];      // broadcast LDS.128
            ffma2(aA0, wA[2 * k],     hv.x);
            ffma2(aA1, wA[2 * k + 1], hv.y);
            ffma2(aB0, wB[2 * k],     hv.x);
            ffma2(aB1, wB[2 * k + 1], hv.y);
        }
        float x = xbuf[s];
        float a0, a1, a2, a3, b0, b1, b2, b3;
        unpack2(aA0, a0, a1); unpack2(aA1, a2, a3);
        unpack2(aB0, b0, b1); unpack2(aB1, b2, b3);
        float gA = (a0 + a1) + (a2 + a3) + __fmaf_rn(x, wihA, bsA);
        float gB = (b0 + b1) + (b2 + b3) + __fmaf_rn(x, wihB, bsB);

        float oA = __shfl_xor_sync(0xffffffffu, gA, 1);
        float oB = __shfl_xor_sync(0xffffffffu, gB, 1);
        float gi = even ? gA : oA;
        float gf = even ? gB : oB;
        float gg = even ? oA : gA;
        float go = even ? oB : gB;

        c_reg   = sigm(gf) * c_reg + sigm(gi) * tanh_f(gg);
        float h = sigm(go) * tanh_f(c_reg);
        if (even) wout[u] = h;
        __syncthreads();
    }

    // ---- bottleneck: hz = sigmoid(h @ enc_linW.T + enc_linb) ----
    const float* hfin = (const float*)hb4[seqlen & 1];
    if (t < 3) {
        float s = enc_linb[t];
        const float* wl = enc_linW + t * Hn;
#pragma unroll 16
        for (int j = 0; j < Hn; j++) s = __fmaf_rn(wl[j], hfin[j], s);
        float z = sigm(s);
        sh_s[t] = z;
        out[1 + 2 * (size_t)Bn * Tn + (size_t)b * 3 + t] = z;
    }
    __syncthreads();

    // hd = hz @ dec_linW.T + dec_linb  (into buffer 0; c carries over)
    if (t < Hn) {
        hb0[t] = dec_linb[t]
               + dec_linW[t * 3 + 0] * sh_s[0]
               + dec_linW[t * 3 + 1] * sh_s[1]
               + dec_linW[t * 3 + 2] * sh_s[2];
    }

    // Decoder weights, FOLDED: W' = dec_Whh + dec_Wih (x) outW,
    // b' = dec_b + dec_Wih*outb.  This removes y->x from the critical path.
    float wihA2 = dec_Wih[rA], wihB2 = dec_Wih[rB];
    {
        const float4* pA = (const float4*)(dec_Whh + rA * Hn);
        const float4* pB = (const float4*)(dec_Whh + rB * Hn);
#pragma unroll
        for (int k = 0; k < 16; k++) {
            float4 a = pA[k], c = pB[k], o = sh_ow4[k];
            wA[2 * k]     = pack2(__fmaf_rn(wihA2, o.x, a.x), __fmaf_rn(wihA2, o.y, a.y));
            wA[2 * k + 1] = pack2(__fmaf_rn(wihA2, o.z, a.z), __fmaf_rn(wihA2, o.w, a.w));
            wB[2 * k]     = pack2(__fmaf_rn(wihB2, o.x, c.x), __fmaf_rn(wihB2, o.y, c.y));
            wB[2 * k + 1] = pack2(__fmaf_rn(wihB2, o.z, c.z), __fmaf_rn(wihB2, o.w, c.w));
        }
    }
    float ob = outb[0];
    bsA = __fmaf_rn(wihA2, ob, dec_b[rA]);
    bsB = __fmaf_rn(wihB2, ob, dec_b[rB]);

    float ow0 = 0.0f, ow1 = 0.0f;
    if (t < 32) { ow0 = sh_ow[lane]; ow1 = sh_ow[lane + 32]; }
    __syncthreads();

    // q = outW . hd + outb  (step-0 correction: x_0 = 0, not y(hd))
    float q = ob;
#pragma unroll 16
    for (int j = 0; j < Hn; j++) q = __fmaf_rn(sh_ow[j], hb0[j], q);

    // ---- decoder: full T steps, pure recurrence; y computed one step late
    //      by warp 0, off the critical path ----
    float  lacc  = 0.0f;
    float* out_y = out + 1 + (size_t)Bn * Tn + (size_t)b * Tn;

    for (int s = 0; s < Tn; s++) {
        const ulonglong2* hq = (const ulonglong2*)hb4[s & 1];
        float* wout = (float*)hb4[(s + 1) & 1];

        // y_{s-1} partial + shuffle chain issued early; latency hides under matvec.
        float yp = 0.0f;
        if (t < 32 && s > 0) {
            const float* hr = (const float*)hb4[s & 1];
            yp = hr[lane] * ow0 + hr[lane + 32] * ow1;
            yp += __shfl_xor_sync(0xffffffffu, yp, 16);
            yp += __shfl_xor_sync(0xffffffffu, yp, 8);
            yp += __shfl_xor_sync(0xffffffffu, yp, 4);
            yp += __shfl_xor_sync(0xffffffffu, yp, 2);
            yp += __shfl_xor_sync(0xffffffffu, yp, 1);
        }

        unsigned long long aA0 = 0ull, aA1 = 0ull, aB0 = 0ull, aB1 = 0ull;
#pragma unroll
        for (int k = 0; k < 16; k++) {
            ulonglong2 hv = hq[k];
            ffma2(aA0, wA[2 * k],     hv.x);
            ffma2(aA1, wA[2 * k + 1], hv.y);
            ffma2(aB0, wB[2 * k],     hv.x);
            ffma2(aB1, wB[2 * k + 1], hv.y);
        }

        if (t == 0 && s > 0) {
            float y = yp + ob;
            out_y[s - 1] = y;
            if (s - 1 < seqlen) {
                float d = xbuf[s - 1] - y;
                lacc = __fmaf_rn(d, d, lacc);
            }
        }

        float a0, a1, a2, a3, b0, b1, b2, b3;
        unpack2(aA0, a0, a1); unpack2(aA1, a2, a3);
        unpack2(aB0, b0, b1); unpack2(aB1, b2, b3);
        float gA = (a0 + a1) + (a2 + a3) + bsA;
        float gB = (b0 + b1) + (b2 + b3) + bsB;
        if (s == 0) {                   // undo fold for x_0 = 0
            gA = __fmaf_rn(-wihA2, q, gA);
            gB = __fmaf_rn(-wihB2, q, gB);
        }

        float oA = __shfl_xor_sync(0xffffffffu, gA, 1);
        float oB = __shfl_xor_sync(0xffffffffu, gB, 1);
        float gi = even ? gA : oA;
        float gf = even ? gB : oB;
        float gg = even ? oA : gA;
        float go = even ? oB : gB;

        c_reg   = sigm(gf) * c_reg + sigm(gi) * tanh_f(gg);
        float h = sigm(go) * tanh_f(c_reg);
        if (even) wout[u] = h;
        __syncthreads();
    }

    // Final y_{T-1} from the last-written buffer (Tn even -> buffer 0).
    if (t < 32) {
        const float* hr = (const float*)hb4[Tn & 1];
        float yp = hr[lane] * ow0 + hr[lane + 32] * ow1;
        yp += __shfl_xor_sync(0xffffffffu, yp, 16);
        yp += __shfl_xor_sync(0xffffffffu, yp, 8);
        yp += __shfl_xor_sync(0xffffffffu, yp, 4);
        yp += __shfl_xor_sync(0xffffffffu, yp, 2);
        yp += __shfl_xor_sync(0xffffffffu, yp, 1);
        if (t == 0) {
            float y = yp + ob;
            out_y[Tn - 1] = y;
            if (Tn - 1 < seqlen) {
                float d = xbuf[Tn - 1] - y;
                lacc = __fmaf_rn(d, d, lacc);
            }
            g_partial[b] = lacc;
        }
    }
}

// ---------- deterministic loss reduction ----------
__global__ void finalize_kernel(const int* __restrict__ seq_lengths,
                                float* __restrict__ out) {
    __shared__ double    ssum[256];
    __shared__ long long scnt[256];
    int tid = threadIdx.x;
    double    s = 0.0;
    long long c = 0;
    for (int i = tid; i < Bn; i += 256) {
        s += (double)g_partial[i];
        c += (long long)seq_lengths[i];
    }
    ssum[tid] = s;
    scnt[tid] = c;
    __syncthreads();
    for (int off = 128; off; off >>= 1) {
        if (tid < off) {
            ssum[tid] += ssum[tid + off];
            scnt[tid] += scnt[tid + off];
        }
        __syncthreads();
    }
    if (tid == 0) out[0] = (float)(ssum[0] / (double)scnt[0]);
}

extern "C" void kernel_launch(void* const* d_in, const int* in_sizes, int n_in,
                              void* d_out, int out_size) {
    const float* padded   = (const float*)d_in[0];
    const int*   seql     = (const int*)  d_in[1];
    const float* enc_Wih  = (const float*)d_in[2];
    const float* enc_Whh  = (const float*)d_in[3];
    const float* enc_b    = (const float*)d_in[4];
    const float* enc_linW = (const float*)d_in[5];
    const float* enc_linb = (const float*)d_in[6];
    const float* dec_linW = (const float*)d_in[7];
    const float* dec_linb = (const float*)d_in[8];
    const float* dec_Wih  = (const float*)d_in[9];
    const float* dec_Whh  = (const float*)d_in[10];
    const float* dec_b    = (const float*)d_in[11];
    const float* outW     = (const float*)d_in[12];
    const float* outb     = (const float*)d_in[13];
    float* out = (float*)d_out;

    // out layout: [loss(1) | padded(B*T) | output(B*T) | hz(B*3)]
    const int n4 = (Bn * Tn) / 4;
    copy_pad_kernel<<<(n4 + 255) / 256, 256>>>((const float4*)padded, out + 1, n4);

    lstm_kernel<<<Bn, 128>>>(padded, seql,
                             enc_Wih, enc_Whh, enc_b,
                             enc_linW, enc_linb,
                             dec_linW, dec_linb,
                             dec_Wih, dec_Whh, dec_b,
                             outW, outb, out);

    finalize_kernel<<<1, 256>>>(seql, out);
}